// round 3
// baseline (speedup 1.0000x reference)
#include <cuda_runtime.h>
#include <math.h>

#define N_WG    512
#define N_COLS  512
#define M_PAIRS 256
#define BATCH   8192
#define BT      32
#define THREADS 512

// Precomputed per-node parameters (6.3 MB total, __device__ globals — no allocs).
// P0 = (cos phi, sin phi, cos theta, sin theta)
// P1 = (insL*sL, cL, insL*cL, sL)   left DC:  vt' = a*vt + i*b*vb ; vb' = i*d*vt + e*vb
// P2 = (insR*sR, cR, insR*cR, sR)   right DC: same structure
__device__ float4 g_P0[N_COLS * M_PAIRS];
__device__ float4 g_P1[N_COLS * M_PAIRS];
__device__ float4 g_P2[N_COLS * M_PAIRS];

__global__ void prep_kernel(const float* __restrict__ thetas,
                            const float* __restrict__ phis,
                            const float* __restrict__ bs_errors,
                            const float* __restrict__ loss_errors) {
    int id = blockIdx.x * blockDim.x + threadIdx.x;
    if (id >= N_COLS * M_PAIRS) return;

    float ph = phis[id];
    float th = thetas[id];
    float pc, ps, tc, ts;
    sincosf(ph, &ps, &pc);
    sincosf(th, &ts, &tc);

    float e0 = bs_errors[2 * id + 0];
    float e1 = bs_errors[2 * id + 1];
    float l0 = loss_errors[2 * id + 0];
    float l1 = loss_errors[2 * id + 1];
    // ins = 10^(loss/20) = exp(ln(10)/20 * loss)
    float ins0 = expf(0.115129254649702f * l0);
    float ins1 = expf(0.115129254649702f * l1);
    const float PI4 = 0.78539816339744831f;
    float s0, c0, s1, c1;
    sincosf(PI4 + e0, &s0, &c0);
    sincosf(PI4 + e1, &s1, &c1);

    g_P0[id] = make_float4(pc, ps, tc, ts);
    g_P1[id] = make_float4(ins0 * s0, c0, ins0 * c0, s0);
    g_P2[id] = make_float4(ins1 * s1, c1, ins1 * c1, s1);
}

// One CTA per 32-batch tile. State in shared memory: float2 v[512][32] = 131 KB.
// Lane = batch index -> every smem access is a contiguous 256 B row (conflict-free),
// every gmem access is coalesced.
extern __shared__ float2 sv[];  // [N_WG][BT]

__global__ void __launch_bounds__(THREADS, 1)
mesh_kernel(const float* __restrict__ x,
            const float* __restrict__ gammas,
            float* __restrict__ out) {
    const int b0   = blockIdx.x * BT;
    const int tid  = threadIdx.x;
    const int lane = tid & 31;
    const int wid  = tid >> 5;   // 0..15

    // init: v = x * exp(i * gamma)
    #pragma unroll 4
    for (int idx = tid; idx < N_WG * BT; idx += THREADS) {
        int wg = idx >> 5;       // BT == 32
        int b  = idx & 31;
        float g = gammas[wg];    // broadcast within warp (wg constant per warp-iter)
        float gs, gc;
        sincosf(g, &gs, &gc);
        float xv = x[wg * BATCH + b0 + b];
        sv[idx] = make_float2(xv * gc, xv * gs);
    }
    __syncthreads();

    for (int c = 0; c < N_COLS; c++) {
        const int odd = c & 1;
        const float4* __restrict__ p0 = g_P0 + c * M_PAIRS;
        const float4* __restrict__ p1 = g_P1 + c * M_PAIRS;
        const float4* __restrict__ p2 = g_P2 + c * M_PAIRS;

        for (int k = wid; k < M_PAIRS; k += 16) {
            if (odd && k == M_PAIRS - 1) continue;  // masked pad pair (0,511)
            const int top = 2 * k + odd;
            const int bot = top + 1;

            const float4 P0 = __ldg(&p0[k]);
            const float4 P1 = __ldg(&p1[k]);
            const float4 P2 = __ldg(&p2[k]);

            float2 vt = sv[top * BT + lane];
            float2 vb = sv[bot * BT + lane];

            // phi phase on top
            float tr = P0.x * vt.x - P0.y * vt.y;
            float ti = P0.x * vt.y + P0.y * vt.x;
            // left DC: vt' = a*vt + i*b*vb ; vb' = i*d*vt + e*vb
            float t2r = P1.x * tr   - P1.y * vb.y;
            float t2i = P1.x * ti   + P1.y * vb.x;
            float b2r = P1.w * vb.x - P1.z * ti;
            float b2i = P1.w * vb.y + P1.z * tr;
            // theta phase on top
            float t3r = P0.z * t2r - P0.w * t2i;
            float t3i = P0.z * t2i + P0.w * t2r;
            // right DC
            float t4r = P2.x * t3r - P2.y * b2i;
            float t4i = P2.x * t3i + P2.y * b2r;
            float b4r = P2.w * b2r - P2.z * t3i;
            float b4i = P2.w * b2i + P2.z * t3r;

            sv[top * BT + lane] = make_float2(t4r, t4i);
            sv[bot * BT + lane] = make_float2(b4r, b4i);
        }
        __syncthreads();
    }

    // out[0] = real, out[1] = imag : float[2][512][8192]
    #pragma unroll 4
    for (int idx = tid; idx < N_WG * BT; idx += THREADS) {
        int wg = idx >> 5;
        int b  = idx & 31;
        float2 v = sv[idx];
        out[wg * BATCH + b0 + b] = v.x;
        out[(size_t)N_WG * BATCH + wg * BATCH + b0 + b] = v.y;
    }
}

extern "C" void kernel_launch(void* const* d_in, const int* in_sizes, int n_in,
                              void* d_out, int out_size) {
    const float* x      = (const float*)d_in[0];
    const float* thetas = (const float*)d_in[1];
    const float* phis   = (const float*)d_in[2];
    const float* gammas = (const float*)d_in[3];
    const float* bs     = (const float*)d_in[4];
    const float* le     = (const float*)d_in[5];
    float* out = (float*)d_out;

    prep_kernel<<<(N_COLS * M_PAIRS + 255) / 256, 256>>>(thetas, phis, bs, le);

    const int smem = N_WG * BT * (int)sizeof(float2);  // 131072 B
    cudaFuncSetAttribute(mesh_kernel, cudaFuncAttributeMaxDynamicSharedMemorySize, smem);
    mesh_kernel<<<BATCH / BT, THREADS, smem>>>(x, gammas, out);
}

// round 4
// speedup vs baseline: 4.1762x; 4.1762x over previous
#include <cuda_runtime.h>
#include <math.h>

#define N_WG    512
#define N_COLS  512
#define M_PAIRS 256
#define BATCH   8192
typedef unsigned long long ull;

// ---------------------------------------------------------------------------
// Device globals (no allocs allowed)
// ---------------------------------------------------------------------------
// Per-node params, interleaved per pair: [c][k][3] float4 (P0,P1,P2) = 6 MB
__device__ float4 g_P[N_COLS * M_PAIRS * 3];
// Full complex transfer matrix A[m][k] (includes gamma phases) = 2 MB
__device__ float2 g_A[N_WG * N_WG];

// ---------------------------------------------------------------------------
// prep: per-node DC / phase coefficients
// P0 = (cos phi, sin phi, cos theta, sin theta)
// P1 = (insL*sL, cL, insL*cL, sL)   left DC
// P2 = (insR*sR, cR, insR*cR, sR)   right DC
// ---------------------------------------------------------------------------
__global__ void prep_kernel(const float* __restrict__ thetas,
                            const float* __restrict__ phis,
                            const float* __restrict__ bs_errors,
                            const float* __restrict__ loss_errors) {
    int id = blockIdx.x * blockDim.x + threadIdx.x;
    if (id >= N_COLS * M_PAIRS) return;

    float pc, ps, tc, ts;
    sincosf(phis[id], &ps, &pc);
    sincosf(thetas[id], &ts, &tc);

    float e0 = bs_errors[2 * id + 0];
    float e1 = bs_errors[2 * id + 1];
    float ins0 = expf(0.115129254649702f * loss_errors[2 * id + 0]);
    float ins1 = expf(0.115129254649702f * loss_errors[2 * id + 1]);
    const float PI4 = 0.78539816339744831f;
    float s0, c0, s1, c1;
    sincosf(PI4 + e0, &s0, &c0);
    sincosf(PI4 + e1, &s1, &c1);

    g_P[id * 3 + 0] = make_float4(pc, ps, tc, ts);
    g_P[id * 3 + 1] = make_float4(ins0 * s0, c0, ins0 * c0, s0);
    g_P[id * 3 + 2] = make_float4(ins1 * s1, c1, ins1 * c1, s1);
}

// ---------------------------------------------------------------------------
// T-build: propagate 4 basis vectors per CTA through the mesh.
// State: sv[512 wg][4 slots] float2 = 16 KB. Params staged per column (12 KB).
// ---------------------------------------------------------------------------
__global__ void __launch_bounds__(512, 1)
tbuild_kernel(const float* __restrict__ gammas) {
    __shared__ float2 sv[N_WG * 4];
    __shared__ float4 sp[M_PAIRS * 3];

    const int tid = threadIdx.x;
    const int b0  = blockIdx.x * 4;

    // init: column j of A starts as e^{i gamma_j} * e_j
    for (int idx = tid; idx < N_WG * 4; idx += 512) {
        int wg = idx >> 2, slot = idx & 3;
        float2 v = make_float2(0.f, 0.f);
        if (wg == b0 + slot) {
            float gs, gc;
            sincosf(gammas[wg], &gs, &gc);
            v = make_float2(gc, gs);
        }
        sv[idx] = v;
    }
    __syncthreads();

    const int k1   = tid >> 2;   // pair 0..127 (second pair = k1+128)
    const int slot = tid & 3;

    for (int c = 0; c < N_COLS; c++) {
        // stage this column's params (768 float4, coalesced)
        const float4* __restrict__ gp = g_P + c * (M_PAIRS * 3);
        for (int idx = tid; idx < M_PAIRS * 3; idx += 512)
            sp[idx] = gp[idx];
        __syncthreads();

        const int odd = c & 1;
        #pragma unroll
        for (int h = 0; h < 2; h++) {
            const int k = k1 + h * 128;
            if (!(odd && k == M_PAIRS - 1)) {
                const int top = 2 * k + odd;
                const int bot = top + 1;
                const float4 P0 = sp[3 * k + 0];
                const float4 P1 = sp[3 * k + 1];
                const float4 P2 = sp[3 * k + 2];

                float2 vt = sv[top * 4 + slot];
                float2 vb = sv[bot * 4 + slot];

                float tr  = P0.x * vt.x - P0.y * vt.y;
                float ti  = P0.x * vt.y + P0.y * vt.x;
                float t2r = P1.x * tr   - P1.y * vb.y;
                float t2i = P1.x * ti   + P1.y * vb.x;
                float b2r = P1.w * vb.x - P1.z * ti;
                float b2i = P1.w * vb.y + P1.z * tr;
                float t3r = P0.z * t2r - P0.w * t2i;
                float t3i = P0.z * t2i + P0.w * t2r;
                float t4r = P2.x * t3r - P2.y * b2i;
                float t4i = P2.x * t3i + P2.y * b2r;
                float b4r = P2.w * b2r - P2.z * t3i;
                float b4i = P2.w * b2i + P2.z * t3r;

                sv[top * 4 + slot] = make_float2(t4r, t4i);
                sv[bot * 4 + slot] = make_float2(b4r, b4i);
            }
        }
        __syncthreads();
    }

    // A[wg][j]
    for (int idx = tid; idx < N_WG * 4; idx += 512) {
        int wg = idx >> 2, j = b0 + (idx & 3);
        g_A[wg * N_WG + j] = sv[idx];
    }
}

// ---------------------------------------------------------------------------
// GEMM: out_re = Re(A)@x, out_im = Im(A)@x using packed fma.rn.f32x2.
// Tile 128 rows x 128 cols per CTA, TK=32. A staged duplicated:
// sA4[row][k] = (ar,ar,ai,ai) so 64-bit packed operands are register pairs.
// ---------------------------------------------------------------------------
#define TM 128
#define TN 128
#define TK 32

__device__ __forceinline__ void fma2(ull& d, ull a, ull b) {
    asm("fma.rn.f32x2 %0, %1, %2, %0;" : "+l"(d) : "l"(a), "l"(b));
}
__device__ __forceinline__ float2 unpk(ull v) {
    float2 f;
    asm("mov.b64 {%0, %1}, %2;" : "=f"(f.x), "=f"(f.y) : "l"(v));
    return f;
}

extern __shared__ char gsmem[];

__global__ void __launch_bounds__(512, 1)
gemm_kernel(const float* __restrict__ x, float* __restrict__ out) {
    float4* sA4 = (float4*)gsmem;                       // [TM][TK] = 64 KB
    float*  sX  = (float*)(gsmem + TM * TK * 16);       // [TK][TN] = 16 KB

    const int tid = threadIdx.x;
    const int m0  = blockIdx.y * TM;
    const int n0  = blockIdx.x * TN;
    const int rg  = tid >> 5;   // 16 row-groups of 8 rows
    const int cg  = tid & 31;   // 32 col-groups of 4 cols

    ull accr[8][2], acci[8][2];
    #pragma unroll
    for (int r = 0; r < 8; r++) {
        accr[r][0] = 0ull; accr[r][1] = 0ull;
        acci[r][0] = 0ull; acci[r][1] = 0ull;
    }

    for (int kt = 0; kt < N_WG; kt += TK) {
        if (kt) __syncthreads();
        // A tile: duplicated (ar,ar,ai,ai)
        for (int idx = tid; idx < TM * TK; idx += 512) {
            int k = idx & (TK - 1), row = idx >> 5;
            float2 a = g_A[(m0 + row) * N_WG + kt + k];
            sA4[row * TK + k] = make_float4(a.x, a.x, a.y, a.y);
        }
        // X tile
        for (int idx = tid; idx < TK * TN; idx += 512) {
            int col = idx & (TN - 1), k = idx >> 7;
            sX[k * TN + col] = x[(size_t)(kt + k) * BATCH + n0 + col];
        }
        __syncthreads();

        #pragma unroll
        for (int k = 0; k < TK; k++) {
            float4 xv = *(const float4*)&sX[k * TN + cg * 4];
            ull x0 = *(const ull*)&xv.x;   // (x0,x1)
            ull x1 = *(const ull*)&xv.z;   // (x2,x3)
            #pragma unroll
            for (int r = 0; r < 8; r++) {
                float4 a4 = sA4[(rg * 8 + r) * TK + k];
                ull ar = *(const ull*)&a4.x;   // (ar,ar)
                ull ai = *(const ull*)&a4.z;   // (ai,ai)
                fma2(accr[r][0], ar, x0);
                fma2(accr[r][1], ar, x1);
                fma2(acci[r][0], ai, x0);
                fma2(acci[r][1], ai, x1);
            }
        }
    }

    const size_t imag_off = (size_t)N_WG * BATCH;
    #pragma unroll
    for (int r = 0; r < 8; r++) {
        size_t base = (size_t)(m0 + rg * 8 + r) * BATCH + n0 + cg * 4;
        float2 r0 = unpk(accr[r][0]), r1 = unpk(accr[r][1]);
        float2 i0 = unpk(acci[r][0]), i1 = unpk(acci[r][1]);
        *(float4*)&out[base]            = make_float4(r0.x, r0.y, r1.x, r1.y);
        *(float4*)&out[imag_off + base] = make_float4(i0.x, i0.y, i1.x, i1.y);
    }
}

// ---------------------------------------------------------------------------
extern "C" void kernel_launch(void* const* d_in, const int* in_sizes, int n_in,
                              void* d_out, int out_size) {
    const float* x      = (const float*)d_in[0];
    const float* thetas = (const float*)d_in[1];
    const float* phis   = (const float*)d_in[2];
    const float* gammas = (const float*)d_in[3];
    const float* bs     = (const float*)d_in[4];
    const float* le     = (const float*)d_in[5];
    float* out = (float*)d_out;

    prep_kernel<<<(N_COLS * M_PAIRS + 255) / 256, 256>>>(thetas, phis, bs, le);
    tbuild_kernel<<<N_WG / 4, 512>>>(gammas);

    const int gsm = TM * TK * 16 + TK * TN * 4;  // 81920 B
    static int attr_set = 0;
    if (!attr_set) {
        cudaFuncSetAttribute(gemm_kernel,
                             cudaFuncAttributeMaxDynamicSharedMemorySize, gsm);
        attr_set = 1;
    }
    dim3 grid(BATCH / TN, N_WG / TM);
    gemm_kernel<<<grid, 512, gsm>>>(x, out);
}